// round 16
// baseline (speedup 1.0000x reference)
#include <cuda_runtime.h>
#include <cuda_fp16.h>
#include <cstdint>
#include <math.h>

#define SEQ 2048
#define DIM 4096
#define NH 32
#define HD 128
#define HID 11008

// ---------------- scratch (no cudaMalloc allowed) ----------------
__device__ float g_h[SEQ * DIM];
__device__ __half g_xnh[SEQ * DIM];
__device__ __half g_qkvh[SEQ * 3 * DIM];
__device__ __half g_ath[SEQ * DIM];
__device__ __half g_gh[SEQ * HID];
__device__ __half g_wqkvh[3 * DIM * DIM];
__device__ __half g_woh[DIM * DIM];
__device__ __half g_w13h[2 * HID * DIM];
__device__ __half g_w2h[DIM * HID];

__device__ __forceinline__ uint32_t smem_u32(const void* p) {
    uint32_t a;
    asm("{ .reg .u64 t; cvta.to.shared.u64 t, %1; cvt.u32.u64 %0, t; }"
        : "=r"(a) : "l"(p));
    return a;
}

#define LDSM_X4(r, addr)                                                      \
    asm volatile("ldmatrix.sync.aligned.m8n8.x4.shared.b16 {%0,%1,%2,%3}, [%4];" \
                 : "=r"((r)[0]), "=r"((r)[1]), "=r"((r)[2]), "=r"((r)[3])     \
                 : "r"(addr))
#define LDSM_X4_T(r, addr)                                                    \
    asm volatile("ldmatrix.sync.aligned.m8n8.x4.trans.shared.b16 {%0,%1,%2,%3}, [%4];" \
                 : "=r"((r)[0]), "=r"((r)[1]), "=r"((r)[2]), "=r"((r)[3])     \
                 : "r"(addr))

#define MMA_FP16(d, a, b0, b1)                                                \
    asm volatile(                                                             \
        "mma.sync.aligned.m16n8k16.row.col.f32.f16.f16.f32 "                  \
        "{%0,%1,%2,%3},{%4,%5,%6,%7},{%8,%9},{%0,%1,%2,%3};"                  \
        : "+f"((d)[0]), "+f"((d)[1]), "+f"((d)[2]), "+f"((d)[3])              \
        : "r"((a)[0]), "r"((a)[1]), "r"((a)[2]), "r"((a)[3]), "r"(b0), "r"(b1))

#define CP16(dst, src)                                                        \
    asm volatile("cp.async.cg.shared.global [%0], [%1], 16;"                  \
                 :: "r"(dst), "l"(src))
#define CP_COMMIT() asm volatile("cp.async.commit_group;")
#define CP_WAIT(n)  asm volatile("cp.async.wait_group %0;" :: "n"(n))

__device__ __forceinline__ uint32_t cvt2h(float x0, float x1) {
    __half2 hh(__float2half_rn(x0), __float2half_rn(x1));
    return *(uint32_t*)&hh;
}
// 64B-row swizzle (GEMM tiles, BK=32 fp16 rows)
__device__ __forceinline__ uint32_t swz(int r, uint32_t cb) {
    return (uint32_t)r * 64 + (cb ^ (((r >> 1) & 3) << 4));
}
// 128B-row swizzle (attention tiles)
__device__ __forceinline__ uint32_t sw128_(uint32_t x) { return x ^ ((x >> 3) & 0x70); }

// ===== Persistent GEMM: C = A*B^T; BM=256 BN=128 BK=32, warp tile 64x64 ====
// MODE 0: fp32 out + residual, 1: fp16 out, 2: swiglu fp16 out
// stage 24KB: A(256x32) 16K | B(128x32) 8K ; 4 stages = 96KB; 1 CTA/SM
#define STAGE_B 24576
#define GEMM_SMEM (4 * STAGE_B)
#define GEMM_GRID 148

template <int MODE>
__global__ void __launch_bounds__(256, 1) gemm_p(
    const __half* __restrict__ Ah, const __half* __restrict__ Bh,
    const float* __restrict__ R, void* __restrict__ Cv, int M, int N, int K) {
    extern __shared__ __align__(1024) char smem[];
    uint32_t sbase = smem_u32(smem);
    int tid = threadIdx.x;
    int lane = tid & 31, wid = tid >> 5;
    int wm = (wid >> 1) * 64;            // 4 M-warps
    int wn = (wid & 1) * 64;             // 2 N-warps
    int nbm = M >> 8, nbn = N >> 7;
    int ntiles = nbm * nbn;
    int NS = K / 32;
    int sub = lane >> 3;

    for (int t = blockIdx.x; t < ntiles; t += gridDim.x) {
        int bm = t % nbm, bn = t / nbm;  // bm-fast: A panel stays in L2
        const __half* Ab = Ah + (size_t)(bm * 256) * K;
        const __half* Bb = Bh + (size_t)(bn * 128) * K;

#define ISSUE(s)                                                              \
    {                                                                         \
        int k0 = (s) * 32;                                                    \
        uint32_t sb = sbase + ((s) & 3) * STAGE_B;                            \
        _Pragma("unroll") for (int it = 0; it < 4; it++) {                    \
            int id = tid + it * 256;                                          \
            int row = id >> 2, kc = id & 3;                                   \
            CP16(sb + swz(row, (uint32_t)kc << 4),                            \
                 Ab + (size_t)row * K + k0 + kc * 8);                         \
        }                                                                     \
        _Pragma("unroll") for (int it = 0; it < 2; it++) {                    \
            int id = tid + it * 256;                                          \
            int row = id >> 2, kc = id & 3;                                   \
            CP16(sb + 16384 + swz(row, (uint32_t)kc << 4),                    \
                 Bb + (size_t)row * K + k0 + kc * 8);                         \
        }                                                                     \
        CP_COMMIT();                                                          \
    }

        float acc[4][8][4];
#pragma unroll
        for (int i = 0; i < 4; i++)
#pragma unroll
            for (int j = 0; j < 8; j++)
#pragma unroll
                for (int tt = 0; tt < 4; tt++) acc[i][j][tt] = 0.f;

        ISSUE(0);
        ISSUE(1);
        ISSUE(2);

        for (int s = 0; s < NS; s++) {
            if (s + 3 < NS) {
                ISSUE(s + 3);
                CP_WAIT(3);
            } else {
                int rem = NS - 1 - s;
                if (rem == 2) { CP_WAIT(2); }
                else if (rem == 1) { CP_WAIT(1); }
                else { CP_WAIT(0); }
            }
            __syncthreads();
            uint32_t sb = sbase + (s & 3) * STAGE_B;
#pragma unroll
            for (int ks = 0; ks < 2; ks++) {
                uint32_t bh[16];
#pragma unroll
                for (int np = 0; np < 4; np++) {
                    int n = wn + np * 16 + (sub >> 1) * 8 + (lane & 7);
                    uint32_t cb = (uint32_t)(ks * 2 + (sub & 1)) << 4;
                    LDSM_X4(&bh[np * 4], sb + 16384 + swz(n, cb));
                }
#pragma unroll
                for (int mi = 0; mi < 4; mi++) {
                    uint32_t a[4];
                    int r = wm + mi * 16 + (lane & 7) + (sub & 1) * 8;
                    uint32_t cb = (uint32_t)(ks * 2 + (sub >> 1)) << 4;
                    LDSM_X4(a, sb + swz(r, cb));
#pragma unroll
                    for (int ni = 0; ni < 8; ni++) {
                        uint32_t* bp = &bh[(ni >> 1) * 4 + (ni & 1) * 2];
                        MMA_FP16(acc[mi][ni], a, bp[0], bp[1]);
                    }
                }
            }
            __syncthreads();
        }

        if (MODE == 2) {
            __half* C = (__half*)Cv;
            int outN = N >> 1;
#pragma unroll
            for (int mi = 0; mi < 4; mi++)
#pragma unroll
                for (int p = 0; p < 4; p++) {
                    int n0 = bn * 128 + wn + p * 16 + 2 * (lane & 3);
                    int j = ((n0 >> 4) << 3) + (n0 & 7);
                    int r0 = bm * 256 + wm + mi * 16 + (lane >> 2);
                    float a0 = acc[mi][2 * p][0], a1 = acc[mi][2 * p][1];
                    float a2 = acc[mi][2 * p][2], a3 = acc[mi][2 * p][3];
                    float b0 = acc[mi][2 * p + 1][0], b1 = acc[mi][2 * p + 1][1];
                    float b2 = acc[mi][2 * p + 1][2], b3 = acc[mi][2 * p + 1][3];
                    float g0 = a0 / (1.f + __expf(-a0)) * b0;
                    float g1 = a1 / (1.f + __expf(-a1)) * b1;
                    float g2 = a2 / (1.f + __expf(-a2)) * b2;
                    float g3 = a3 / (1.f + __expf(-a3)) * b3;
                    *(uint32_t*)(C + (size_t)r0 * outN + j) = cvt2h(g0, g1);
                    *(uint32_t*)(C + (size_t)(r0 + 8) * outN + j) = cvt2h(g2, g3);
                }
        } else {
#pragma unroll
            for (int mi = 0; mi < 4; mi++)
#pragma unroll
                for (int ni = 0; ni < 8; ni++) {
                    int r0 = bm * 256 + wm + mi * 16 + (lane >> 2);
                    int col = bn * 128 + wn + ni * 8 + (lane & 3) * 2;
                    if (MODE == 1) {
                        __half* C = (__half*)Cv;
                        *(uint32_t*)(C + (size_t)r0 * N + col) =
                            cvt2h(acc[mi][ni][0], acc[mi][ni][1]);
                        *(uint32_t*)(C + (size_t)(r0 + 8) * N + col) =
                            cvt2h(acc[mi][ni][2], acc[mi][ni][3]);
                    } else {
                        float* C = (float*)Cv;
                        float* p0 = C + (size_t)r0 * N + col;
                        float* p1 = p0 + 8 * (size_t)N;
                        const float* q0 = R + (size_t)r0 * N + col;
                        const float* q1 = q0 + 8 * (size_t)N;
                        float2 v0 = {acc[mi][ni][0] + q0[0], acc[mi][ni][1] + q0[1]};
                        float2 v1 = {acc[mi][ni][2] + q1[0], acc[mi][ni][3] + q1[1]};
                        *(float2*)p0 = v0;
                        *(float2*)p1 = v1;
                    }
                }
        }
#undef ISSUE
    }
}

// ---------------- weight convert: fp32 -> fp16 ----------------
__global__ void convert_kernel(const float* __restrict__ w,
                               __half* __restrict__ h, int n4) {
    int i = blockIdx.x * 256 + threadIdx.x;
    if (i < n4) {
        float4 v = ((const float4*)w)[i];
        ((uint2*)h)[i] = make_uint2(cvt2h(v.x, v.y), cvt2h(v.z, v.w));
    }
}

// w1/w3 -> interleaved w13 (8-row blocks: [w1 j..j+7][w3 j..j+7])
__global__ void convert_w13(const float* __restrict__ w1,
                            const float* __restrict__ w3,
                            __half* __restrict__ o, int n4) {
    int i = blockIdx.x * 256 + threadIdx.x;
    if (i < n4) {
        int row = i / (DIM / 4);
        int c4 = i % (DIM / 4);
        int orow = ((row >> 3) << 4) + (row & 7);
        float4 v = ((const float4*)w1)[i];
        ((uint2*)(o + (size_t)orow * DIM))[c4] =
            make_uint2(cvt2h(v.x, v.y), cvt2h(v.z, v.w));
        float4 u = ((const float4*)w3)[i];
        ((uint2*)(o + (size_t)(orow + 8) * DIM))[c4] =
            make_uint2(cvt2h(u.x, u.y), cvt2h(u.z, u.w));
    }
}

// ---------------- RMSNorm -> fp16 ----------------
__global__ void rmsnorm_h(const float* __restrict__ x,
                          const float* __restrict__ w,
                          __half* __restrict__ oh) {
    int row = blockIdx.x;
    int tid = threadIdx.x;
    const float4* xr = (const float4*)(x + (size_t)row * DIM);
    __shared__ float red[8];
    float4 vals[4];
    float ss = 0.f;
#pragma unroll
    for (int i = 0; i < 4; i++) {
        float4 v = xr[tid + i * 256];
        vals[i] = v;
        ss += v.x * v.x + v.y * v.y + v.z * v.z + v.w * v.w;
    }
#pragma unroll
    for (int off = 16; off; off >>= 1) ss += __shfl_xor_sync(~0u, ss, off);
    if ((tid & 31) == 0) red[tid >> 5] = ss;
    __syncthreads();
    float tot = 0.f;
#pragma unroll
    for (int i = 0; i < 8; i++) tot += red[i];
    float rs = rsqrtf(tot * (1.0f / DIM) + 1e-5f);
    const float4* wr = (const float4*)w;
    uint2* ohr = (uint2*)(oh + (size_t)row * DIM);
#pragma unroll
    for (int i = 0; i < 4; i++) {
        int c = tid + i * 256;
        float4 v = vals[i];
        float4 wv = wr[c];
        v.x *= rs * wv.x; v.y *= rs * wv.y; v.z *= rs * wv.z; v.w *= rs * wv.w;
        ohr[c] = make_uint2(cvt2h(v.x, v.y), cvt2h(v.z, v.w));
    }
}

// ---------------- RoPE on fp16 qkv; Q also scaled by log2e/sqrt(hd) --------
#define QSCALE 0.12751744935309278f
__global__ void rotary_h(__half* __restrict__ qkv,
                         const float* __restrict__ cosb,
                         const float* __restrict__ sinb) {
    int idx = blockIdx.x * 256 + threadIdx.x;
    int s = idx >> 11;
    int rem = idx & 2047;
    int i = rem & 63;
    int hh = rem >> 6;
    float c = cosb[s * 64 + i];
    float sn = sinb[s * 64 + i];
    size_t base = (size_t)s * (3 * DIM) + blockIdx.y * DIM + hh * HD + 2 * i;
    __half2* p = (__half2*)(qkv + base);
    float2 v = __half22float2(*p);
    float o0 = v.x * c - v.y * sn;
    float o1 = v.x * sn + v.y * c;
    if (blockIdx.y == 0) { o0 *= QSCALE; o1 *= QSCALE; }
    *p = __floats2half2_rn(o0, o1);
}

// ---------------- flash attention (fp16 MMA, online softmax) ---------------
#define FA_SMEM 98304

__global__ void __launch_bounds__(256, 1) flash_attn(
    const __half* __restrict__ QKV, __half* __restrict__ O) {
    extern __shared__ __align__(1024) char smem[];
    uint32_t sb = smem_u32(smem);
    int tid = threadIdx.x, lane = tid & 31, w = tid >> 5;
    int h = blockIdx.y;
    int qb = gridDim.x - 1 - blockIdx.x;   // heavy tiles first
    int qbase = qb * 128;
    const int LD = 3 * DIM;

    const __half* Qg = QKV + (size_t)qbase * LD + h * HD;
    const __half* Kg = QKV + DIM + h * HD;
    const __half* Vg = QKV + 2 * DIM + h * HD;

#define ISSUE_KV(i, b)                                                        \
    {                                                                         \
        int kv0_ = (i) * 64;                                                  \
        uint32_t kb_ = sb + 32768 + (b) * 32768;                              \
        _Pragma("unroll") for (int it = 0; it < 4; it++) {                    \
            int id = tid + it * 256;                                          \
            int row = id >> 4, ch = id & 15;                                  \
            uint32_t o_ = (uint32_t)(ch >> 3) * 8192 +                        \
                          sw128_(row * 128 + (ch & 7) * 16);                  \
            const __half* ksrc = Kg + (size_t)(kv0_ + row) * LD + ch * 8;     \
            const __half* vsrc = Vg + (size_t)(kv0_ + row) * LD + ch * 8;     \
            CP16(kb_ + o_, ksrc);                                             \
            CP16(kb_ + 16384 + o_, vsrc);                                     \
        }                                                                     \
    }

#pragma unroll
    for (int it = 0; it < 8; it++) {
        int id = tid + it * 256;
        int row = id >> 4, ch = id & 15;
        uint32_t dst = sb + (uint32_t)(ch >> 3) * 16384 +
                       sw128_(row * 128 + (ch & 7) * 16);
        CP16(dst, Qg + (size_t)row * LD + ch * 8);
    }
    ISSUE_KV(0, 0);
    CP_COMMIT();

    float oacc[16][4];
#pragma unroll
    for (int j = 0; j < 16; j++)
#pragma unroll
        for (int t = 0; t < 4; t++) oacc[j][t] = 0.f;
    float m0 = -1e30f, m1 = -1e30f, l0 = 0.f, l1 = 0.f;
    uint32_t qf[8][4];

    int nkb = qb * 2 + 2;
    int sub = lane >> 3;
    int wrow = qbase + w * 16;

    for (int i = 0; i < nkb; i++) {
        int b = i & 1;
        if (i + 1 < nkb) {
            ISSUE_KV(i + 1, b ^ 1);
            CP_COMMIT();
            CP_WAIT(1);
        } else {
            CP_WAIT(0);
        }
        __syncthreads();
        if (i == 0) {
#pragma unroll
            for (int kt = 0; kt < 8; kt++) {
                int r = w * 16 + (lane & 7) + (sub & 1) * 8;
                uint32_t ch = (uint32_t)((kt & 3) * 2 + (sub >> 1));
                uint32_t addr = sb + (uint32_t)(kt >> 2) * 16384 +
                                sw128_(r * 128 + ch * 16);
                LDSM_X4(qf[kt], addr);
            }
        }
        int kv0 = i * 64;
        if (kv0 <= wrow + 15) {
            float sacc[8][4];
#pragma unroll
            for (int j = 0; j < 8; j++)
#pragma unroll
                for (int t = 0; t < 4; t++) sacc[j][t] = 0.f;
            uint32_t Kb = sb + 32768 + b * 32768;
#pragma unroll
            for (int ng = 0; ng < 4; ng++) {
                int nr = ng * 16 + (sub >> 1) * 8 + (lane & 7);
#pragma unroll
                for (int kt = 0; kt < 8; kt++) {
                    uint32_t bb[4];
                    uint32_t ch = (uint32_t)((kt & 3) * 2 + (sub & 1));
                    uint32_t addr = Kb + (uint32_t)(kt >> 2) * 8192 +
                                    sw128_(nr * 128 + ch * 16);
                    LDSM_X4(bb, addr);
                    MMA_FP16(sacc[ng * 2], qf[kt], bb[0], bb[1]);
                    MMA_FP16(sacc[ng * 2 + 1], qf[kt], bb[2], bb[3]);
                }
            }
            int r0 = wrow + (lane >> 2), r1 = r0 + 8;
            if (kv0 + 63 > r0) {
#pragma unroll
                for (int j = 0; j < 8; j++) {
                    int c = kv0 + j * 8 + 2 * (lane & 3);
                    if (c > r0) sacc[j][0] = -1e30f;
                    if (c + 1 > r0) sacc[j][1] = -1e30f;
                    if (c > r1) sacc[j][2] = -1e30f;
                    if (c + 1 > r1) sacc[j][3] = -1e30f;
                }
            }
            float mx0 = -1e30f, mx1 = -1e30f;
#pragma unroll
            for (int j = 0; j < 8; j++) {
                mx0 = fmaxf(mx0, fmaxf(sacc[j][0], sacc[j][1]));
                mx1 = fmaxf(mx1, fmaxf(sacc[j][2], sacc[j][3]));
            }
            mx0 = fmaxf(mx0, __shfl_xor_sync(~0u, mx0, 1));
            mx0 = fmaxf(mx0, __shfl_xor_sync(~0u, mx0, 2));
            mx1 = fmaxf(mx1, __shfl_xor_sync(~0u, mx1, 1));
            mx1 = fmaxf(mx1, __shfl_xor_sync(~0u, mx1, 2));
            float m0n = fmaxf(m0, mx0), m1n = fmaxf(m1, mx1);
            float c0 = exp2f(m0 - m0n), c1 = exp2f(m1 - m1n);
            float rs0 = 0.f, rs1 = 0.f;
#pragma unroll
            for (int j = 0; j < 8; j++) {
                sacc[j][0] = exp2f(sacc[j][0] - m0n);
                sacc[j][1] = exp2f(sacc[j][1] - m0n);
                sacc[j][2] = exp2f(sacc[j][2] - m1n);
                sacc[j][3] = exp2f(sacc[j][3] - m1n);
                rs0 += sacc[j][0] + sacc[j][1];
                rs1 += sacc[j][2] + sacc[j][3];
            }
            rs0 += __shfl_xor_sync(~0u, rs0, 1);
            rs0 += __shfl_xor_sync(~0u, rs0, 2);
            rs1 += __shfl_xor_sync(~0u, rs1, 1);
            rs1 += __shfl_xor_sync(~0u, rs1, 2);
            l0 = l0 * c0 + rs0;
            l1 = l1 * c1 + rs1;
            m0 = m0n;
            m1 = m1n;
#pragma unroll
            for (int j = 0; j < 16; j++) {
                oacc[j][0] *= c0; oacc[j][1] *= c0;
                oacc[j][2] *= c1; oacc[j][3] *= c1;
            }
            uint32_t Vb = Kb + 16384;
#pragma unroll
            for (int kt = 0; kt < 4; kt++) {
                uint32_t a[4];
                a[0] = cvt2h(sacc[2 * kt][0], sacc[2 * kt][1]);
                a[1] = cvt2h(sacc[2 * kt][2], sacc[2 * kt][3]);
                a[2] = cvt2h(sacc[2 * kt + 1][0], sacc[2 * kt + 1][1]);
                a[3] = cvt2h(sacc[2 * kt + 1][2], sacc[2 * kt + 1][3]);
                int kr = kt * 16 + (lane & 7) + ((lane >> 3) & 1) * 8;
#pragma unroll
                for (int dp = 0; dp < 8; dp++) {
                    int dim = dp * 16 + ((lane >> 4) & 1) * 8;
                    uint32_t addr = Vb + (uint32_t)(dim >> 6) * 8192 +
                                    sw128_(kr * 128 + ((dim & 63) >> 3) * 16);
                    uint32_t vv[4];
                    LDSM_X4_T(vv, addr);
                    MMA_FP16(oacc[dp * 2], a, vv[0], vv[1]);
                    MMA_FP16(oacc[dp * 2 + 1], a, vv[2], vv[3]);
                }
            }
        }
        __syncthreads();
    }

    float i0 = 1.f / l0, i1 = 1.f / l1;
    int r0g = qbase + w * 16 + (lane >> 2);
#pragma unroll
    for (int j = 0; j < 16; j++) {
        int col = h * HD + j * 8 + 2 * (lane & 3);
        *(uint32_t*)(O + (size_t)r0g * DIM + col) =
            cvt2h(oacc[j][0] * i0, oacc[j][1] * i0);
        *(uint32_t*)(O + (size_t)(r0g + 8) * DIM + col) =
            cvt2h(oacc[j][2] * i1, oacc[j][3] * i1);
    }
#undef ISSUE_KV
}

// ---------------- launch ----------------
extern "C" void kernel_launch(void* const* d_in, const int* in_sizes, int n_in,
                              void* d_out, int out_size) {
    const float* x   = (const float*)d_in[0];
    const float* fc  = (const float*)d_in[1];
    const float* fs  = (const float*)d_in[2];
    const float* anw = (const float*)d_in[4];
    const float* wq  = (const float*)d_in[5];
    const float* wk  = (const float*)d_in[6];
    const float* wv  = (const float*)d_in[7];
    const float* wo  = (const float*)d_in[8];
    const float* fnw = (const float*)d_in[9];
    const float* w1  = (const float*)d_in[10];
    const float* w2  = (const float*)d_in[11];
    const float* w3  = (const float*)d_in[12];
    float* out = (float*)d_out;

    float* h;
    __half *xnh, *qkvh, *ath, *gh;
    __half *wqkvh, *woh, *w13h, *w2h;
    cudaGetSymbolAddress((void**)&h,     g_h);
    cudaGetSymbolAddress((void**)&xnh,   g_xnh);
    cudaGetSymbolAddress((void**)&qkvh,  g_qkvh);
    cudaGetSymbolAddress((void**)&ath,   g_ath);
    cudaGetSymbolAddress((void**)&gh,    g_gh);
    cudaGetSymbolAddress((void**)&wqkvh, g_wqkvh);
    cudaGetSymbolAddress((void**)&woh,   g_woh);
    cudaGetSymbolAddress((void**)&w13h,  g_w13h);
    cudaGetSymbolAddress((void**)&w2h,   g_w2h);

    cudaFuncSetAttribute(gemm_p<0>, cudaFuncAttributeMaxDynamicSharedMemorySize, GEMM_SMEM);
    cudaFuncSetAttribute(gemm_p<1>, cudaFuncAttributeMaxDynamicSharedMemorySize, GEMM_SMEM);
    cudaFuncSetAttribute(gemm_p<2>, cudaFuncAttributeMaxDynamicSharedMemorySize, GEMM_SMEM);
    cudaFuncSetAttribute(flash_attn, cudaFuncAttributeMaxDynamicSharedMemorySize, FA_SMEM);

    const int ndd4 = DIM * DIM / 4;
    const int nhd4 = HID * DIM / 4;
    convert_kernel<<<(ndd4 + 255) / 256, 256>>>(wq, wqkvh, ndd4);
    convert_kernel<<<(ndd4 + 255) / 256, 256>>>(wk, wqkvh + (size_t)DIM * DIM, ndd4);
    convert_kernel<<<(ndd4 + 255) / 256, 256>>>(wv, wqkvh + (size_t)2 * DIM * DIM, ndd4);
    convert_kernel<<<(ndd4 + 255) / 256, 256>>>(wo, woh, ndd4);
    convert_w13<<<(nhd4 + 255) / 256, 256>>>(w1, w3, w13h, nhd4);
    convert_kernel<<<(nhd4 + 255) / 256, 256>>>(w2, w2h, nhd4);

    // 1. xn = rmsnorm(x)
    rmsnorm_h<<<SEQ, 256>>>(x, anw, xnh);
    // 2. qkv = xn @ [wq;wk;wv]^T (fp16 out)
    gemm_p<1><<<GEMM_GRID, 256, GEMM_SMEM>>>(xnh, wqkvh, nullptr, qkvh, SEQ, 3 * DIM, DIM);
    // 3. rope
    rotary_h<<<dim3(SEQ * NH * 64 / 256, 2), 256>>>(qkvh, fc, fs);
    // 4. flash attention
    flash_attn<<<dim3(SEQ / 128, NH), 256, FA_SMEM>>>(qkvh, ath);
    // 5. h = x + attn @ wo^T
    gemm_p<0><<<GEMM_GRID, 256, GEMM_SMEM>>>(ath, woh, x, h, SEQ, DIM, DIM);
    // 6. hn = rmsnorm(h)
    rmsnorm_h<<<SEQ, 256>>>(h, fnw, xnh);
    // 7+8. g = silu(hn@w1^T) * (hn@w3^T)   (fused swiglu epilogue)
    gemm_p<2><<<GEMM_GRID, 256, GEMM_SMEM>>>(xnh, w13h, nullptr, gh, SEQ, 2 * HID, DIM);
    // 9. out = h + g @ w2^T
    gemm_p<0><<<GEMM_GRID, 256, GEMM_SMEM>>>(gh, w2h, h, out, SEQ, DIM, HID);
}

// round 17
// speedup vs baseline: 1.1471x; 1.1471x over previous
#include <cuda_runtime.h>
#include <cuda_fp16.h>
#include <cstdint>
#include <math.h>

#define SEQ 2048
#define DIM 4096
#define NH 32
#define HD 128
#define HID 11008

// ---------------- scratch (no cudaMalloc allowed) ----------------
__device__ float g_h[SEQ * DIM];
__device__ __half g_xnh[SEQ * DIM];
__device__ __half g_qkvh[SEQ * 3 * DIM];
__device__ __half g_ath[SEQ * DIM];
__device__ __half g_gh[SEQ * HID];
__device__ __half g_wqkvh[3 * DIM * DIM];
__device__ __half g_woh[DIM * DIM];
__device__ __half g_w13h[2 * HID * DIM];
__device__ __half g_w2h[DIM * HID];

__device__ __forceinline__ uint32_t smem_u32(const void* p) {
    uint32_t a;
    asm("{ .reg .u64 t; cvta.to.shared.u64 t, %1; cvt.u32.u64 %0, t; }"
        : "=r"(a) : "l"(p));
    return a;
}

#define LDSM_X4(r, addr)                                                      \
    asm volatile("ldmatrix.sync.aligned.m8n8.x4.shared.b16 {%0,%1,%2,%3}, [%4];" \
                 : "=r"((r)[0]), "=r"((r)[1]), "=r"((r)[2]), "=r"((r)[3])     \
                 : "r"(addr))
#define LDSM_X4_T(r, addr)                                                    \
    asm volatile("ldmatrix.sync.aligned.m8n8.x4.trans.shared.b16 {%0,%1,%2,%3}, [%4];" \
                 : "=r"((r)[0]), "=r"((r)[1]), "=r"((r)[2]), "=r"((r)[3])     \
                 : "r"(addr))

#define MMA_FP16(d, a, b0, b1)                                                \
    asm volatile(                                                             \
        "mma.sync.aligned.m16n8k16.row.col.f32.f16.f16.f32 "                  \
        "{%0,%1,%2,%3},{%4,%5,%6,%7},{%8,%9},{%0,%1,%2,%3};"                  \
        : "+f"((d)[0]), "+f"((d)[1]), "+f"((d)[2]), "+f"((d)[3])              \
        : "r"((a)[0]), "r"((a)[1]), "r"((a)[2]), "r"((a)[3]), "r"(b0), "r"(b1))

#define CP16(dst, src)                                                        \
    asm volatile("cp.async.cg.shared.global [%0], [%1], 16;"                  \
                 :: "r"(dst), "l"(src))
#define CP_COMMIT() asm volatile("cp.async.commit_group;")
#define CP_WAIT(n)  asm volatile("cp.async.wait_group %0;" :: "n"(n))

__device__ __forceinline__ uint32_t cvt2h(float x0, float x1) {
    __half2 hh(__float2half_rn(x0), __float2half_rn(x1));
    return *(uint32_t*)&hh;
}
// 64B-row swizzle (GEMM tiles, BK=32 fp16 rows)
__device__ __forceinline__ uint32_t swz(int r, uint32_t cb) {
    return (uint32_t)r * 64 + (cb ^ (((r >> 1) & 3) << 4));
}
// 128B-row swizzle (attention tiles)
__device__ __forceinline__ uint32_t sw128_(uint32_t x) { return x ^ ((x >> 3) & 0x70); }

#define QSCALE 0.12751744935309278f  // log2(e)/sqrt(128)

// ===== Persistent GEMM: C = A*B^T; BM=BN=128 BK=32, warp tile 64x32 ========
// MODE 0: fp32 out + residual, 1: fp16 out, 2: swiglu fp16 out,
// MODE 3: fp16 out + fused RoPE (QKV)
// stage 16KB: A 8K | B 8K ; 4 stages = 64KB; 2 CTAs/SM
#define STAGE_B 16384
#define GEMM_SMEM (4 * STAGE_B)
#define GEMM_GRID 296

template <int MODE>
__global__ void __launch_bounds__(256, 2) gemm_p(
    const __half* __restrict__ Ah, const __half* __restrict__ Bh,
    const float* __restrict__ R,
    const float* __restrict__ Cb, const float* __restrict__ Sb,
    void* __restrict__ Cv, int M, int N, int K) {
    extern __shared__ __align__(1024) char smem[];
    uint32_t sbase = smem_u32(smem);
    int tid = threadIdx.x;
    int lane = tid & 31, wid = tid >> 5;
    int wm = (wid >> 2) * 64;
    int wn = (wid & 3) * 32;
    int nbm = M >> 7, nbn = N >> 7;
    int ntiles = nbm * nbn;
    int NS = K / 32;
    int sub = lane >> 3;

    for (int t = blockIdx.x; t < ntiles; t += gridDim.x) {
        int bm = t % nbm, bn = t / nbm;  // bm-fast: A panel stays in L2
        const __half* Ab = Ah + (size_t)(bm * 128) * K;
        const __half* Bb = Bh + (size_t)(bn * 128) * K;

#define ISSUE(s)                                                              \
    {                                                                         \
        int k0 = (s) * 32;                                                    \
        uint32_t sb = sbase + ((s) & 3) * STAGE_B;                            \
        _Pragma("unroll") for (int it = 0; it < 4; it++) {                    \
            int id = tid + (it & 1) * 256;                                    \
            int row = id >> 2, kc = id & 3;                                   \
            const __half* src = ((it >> 1) == 0 ? Ab : Bb) +                  \
                                (size_t)row * K + k0 + kc * 8;                \
            uint32_t dst = sb + (uint32_t)(it >> 1) * 8192 +                  \
                           swz(row, (uint32_t)kc << 4);                       \
            CP16(dst, src);                                                   \
        }                                                                     \
        CP_COMMIT();                                                          \
    }

        float acc[4][4][4];
#pragma unroll
        for (int i = 0; i < 4; i++)
#pragma unroll
            for (int j = 0; j < 4; j++)
#pragma unroll
                for (int tt = 0; tt < 4; tt++) acc[i][j][tt] = 0.f;

        ISSUE(0);
        ISSUE(1);
        ISSUE(2);

        for (int s = 0; s < NS; s++) {
            if (s + 3 < NS) ISSUE(s + 3);
            int rem = NS - 1 - s;
            if (rem >= 3) { CP_WAIT(3); }
            else if (rem == 2) { CP_WAIT(2); }
            else if (rem == 1) { CP_WAIT(1); }
            else { CP_WAIT(0); }
            __syncthreads();
            uint32_t sb = sbase + (s & 3) * STAGE_B;
#pragma unroll
            for (int ks = 0; ks < 2; ks++) {
                uint32_t bh[8];
#pragma unroll
                for (int np = 0; np < 2; np++) {
                    int n = wn + np * 16 + (sub >> 1) * 8 + (lane & 7);
                    uint32_t cb = (uint32_t)(ks * 2 + (sub & 1)) << 4;
                    LDSM_X4(&bh[np * 4], sb + 8192 + swz(n, cb));
                }
#pragma unroll
                for (int mi = 0; mi < 4; mi++) {
                    uint32_t a[4];
                    int r = wm + mi * 16 + (lane & 7) + (sub & 1) * 8;
                    uint32_t cb = (uint32_t)(ks * 2 + (sub >> 1)) << 4;
                    LDSM_X4(a, sb + swz(r, cb));
#pragma unroll
                    for (int ni = 0; ni < 4; ni++) {
                        uint32_t* bp = &bh[(ni >> 1) * 4 + (ni & 1) * 2];
                        MMA_FP16(acc[mi][ni], a, bp[0], bp[1]);
                    }
                }
            }
            __syncthreads();
        }

        if (MODE == 2) {
            // swiglu epilogue: interleaved w13 rows -> g = silu(g1)*g3
            __half* C = (__half*)Cv;
            int outN = N >> 1;
#pragma unroll
            for (int mi = 0; mi < 4; mi++)
#pragma unroll
                for (int p = 0; p < 2; p++) {
                    int n0 = bn * 128 + wn + p * 16 + 2 * (lane & 3);
                    int j = ((n0 >> 4) << 3) + (n0 & 7);
                    int r0 = bm * 128 + wm + mi * 16 + (lane >> 2);
                    float a0 = acc[mi][2 * p][0], a1 = acc[mi][2 * p][1];
                    float a2 = acc[mi][2 * p][2], a3 = acc[mi][2 * p][3];
                    float b0 = acc[mi][2 * p + 1][0], b1 = acc[mi][2 * p + 1][1];
                    float b2 = acc[mi][2 * p + 1][2], b3 = acc[mi][2 * p + 1][3];
                    float g0 = a0 / (1.f + __expf(-a0)) * b0;
                    float g1 = a1 / (1.f + __expf(-a1)) * b1;
                    float g2 = a2 / (1.f + __expf(-a2)) * b2;
                    float g3 = a3 / (1.f + __expf(-a3)) * b3;
                    *(uint32_t*)(C + (size_t)r0 * outN + j) = cvt2h(g0, g1);
                    *(uint32_t*)(C + (size_t)(r0 + 8) * outN + j) = cvt2h(g2, g3);
                }
        } else if (MODE == 3) {
            // QKV epilogue with fused RoPE on q (scaled) and k
            __half* C = (__half*)Cv;
#pragma unroll
            for (int mi = 0; mi < 4; mi++)
#pragma unroll
                for (int ni = 0; ni < 4; ni++) {
                    int r0 = bm * 128 + wm + mi * 16 + (lane >> 2);
                    int col = bn * 128 + wn + ni * 8 + 2 * (lane & 3);
                    float v0 = acc[mi][ni][0], v1 = acc[mi][ni][1];
                    float v2 = acc[mi][ni][2], v3 = acc[mi][ni][3];
                    if (col < 2 * DIM) {
                        int i = (col & 127) >> 1;
                        float c0 = Cb[r0 * 64 + i], s0 = Sb[r0 * 64 + i];
                        float c1 = Cb[(r0 + 8) * 64 + i], s1 = Sb[(r0 + 8) * 64 + i];
                        float t0 = v0 * c0 - v1 * s0, t1 = v0 * s0 + v1 * c0;
                        float t2 = v2 * c1 - v3 * s1, t3 = v2 * s1 + v3 * c1;
                        if (col < DIM) {
                            t0 *= QSCALE; t1 *= QSCALE;
                            t2 *= QSCALE; t3 *= QSCALE;
                        }
                        v0 = t0; v1 = t1; v2 = t2; v3 = t3;
                    }
                    *(uint32_t*)(C + (size_t)r0 * N + col) = cvt2h(v0, v1);
                    *(uint32_t*)(C + (size_t)(r0 + 8) * N + col) = cvt2h(v2, v3);
                }
        } else {
#pragma unroll
            for (int mi = 0; mi < 4; mi++)
#pragma unroll
                for (int ni = 0; ni < 4; ni++) {
                    int r0 = bm * 128 + wm + mi * 16 + (lane >> 2);
                    int col = bn * 128 + wn + ni * 8 + (lane & 3) * 2;
                    if (MODE == 1) {
                        __half* C = (__half*)Cv;
                        *(uint32_t*)(C + (size_t)r0 * N + col) =
                            cvt2h(acc[mi][ni][0], acc[mi][ni][1]);
                        *(uint32_t*)(C + (size_t)(r0 + 8) * N + col) =
                            cvt2h(acc[mi][ni][2], acc[mi][ni][3]);
                    } else {
                        float* C = (float*)Cv;
                        float* p0 = C + (size_t)r0 * N + col;
                        float* p1 = p0 + 8 * (size_t)N;
                        const float* q0 = R + (size_t)r0 * N + col;
                        const float* q1 = q0 + 8 * (size_t)N;
                        float2 v0 = {acc[mi][ni][0] + q0[0], acc[mi][ni][1] + q0[1]};
                        float2 v1 = {acc[mi][ni][2] + q1[0], acc[mi][ni][3] + q1[1]};
                        *(float2*)p0 = v0;
                        *(float2*)p1 = v1;
                    }
                }
        }
#undef ISSUE
    }
}

// ---------------- weight convert: fp32 -> fp16 ----------------
__global__ void convert_kernel(const float* __restrict__ w,
                               __half* __restrict__ h, int n4) {
    int i = blockIdx.x * 256 + threadIdx.x;
    if (i < n4) {
        float4 v = ((const float4*)w)[i];
        ((uint2*)h)[i] = make_uint2(cvt2h(v.x, v.y), cvt2h(v.z, v.w));
    }
}

// w1/w3 -> interleaved w13 (8-row blocks: [w1 j..j+7][w3 j..j+7])
__global__ void convert_w13(const float* __restrict__ w1,
                            const float* __restrict__ w3,
                            __half* __restrict__ o, int n4) {
    int i = blockIdx.x * 256 + threadIdx.x;
    if (i < n4) {
        int row = i / (DIM / 4);
        int c4 = i % (DIM / 4);
        int orow = ((row >> 3) << 4) + (row & 7);
        float4 v = ((const float4*)w1)[i];
        ((uint2*)(o + (size_t)orow * DIM))[c4] =
            make_uint2(cvt2h(v.x, v.y), cvt2h(v.z, v.w));
        float4 u = ((const float4*)w3)[i];
        ((uint2*)(o + (size_t)(orow + 8) * DIM))[c4] =
            make_uint2(cvt2h(u.x, u.y), cvt2h(u.z, u.w));
    }
}

// ---------------- RMSNorm -> fp16 ----------------
__global__ void rmsnorm_h(const float* __restrict__ x,
                          const float* __restrict__ w,
                          __half* __restrict__ oh) {
    int row = blockIdx.x;
    int tid = threadIdx.x;
    const float4* xr = (const float4*)(x + (size_t)row * DIM);
    __shared__ float red[8];
    float4 vals[4];
    float ss = 0.f;
#pragma unroll
    for (int i = 0; i < 4; i++) {
        float4 v = xr[tid + i * 256];
        vals[i] = v;
        ss += v.x * v.x + v.y * v.y + v.z * v.z + v.w * v.w;
    }
#pragma unroll
    for (int off = 16; off; off >>= 1) ss += __shfl_xor_sync(~0u, ss, off);
    if ((tid & 31) == 0) red[tid >> 5] = ss;
    __syncthreads();
    float tot = 0.f;
#pragma unroll
    for (int i = 0; i < 8; i++) tot += red[i];
    float rs = rsqrtf(tot * (1.0f / DIM) + 1e-5f);
    const float4* wr = (const float4*)w;
    uint2* ohr = (uint2*)(oh + (size_t)row * DIM);
#pragma unroll
    for (int i = 0; i < 4; i++) {
        int c = tid + i * 256;
        float4 v = vals[i];
        float4 wv = wr[c];
        v.x *= rs * wv.x; v.y *= rs * wv.y; v.z *= rs * wv.z; v.w *= rs * wv.w;
        ohr[c] = make_uint2(cvt2h(v.x, v.y), cvt2h(v.z, v.w));
    }
}

// ---------------- flash attention (fp16 MMA, online softmax) ---------------
#define FA_SMEM 98304

__global__ void __launch_bounds__(256, 1) flash_attn(
    const __half* __restrict__ QKV, __half* __restrict__ O) {
    extern __shared__ __align__(1024) char smem[];
    uint32_t sb = smem_u32(smem);
    int tid = threadIdx.x, lane = tid & 31, w = tid >> 5;
    int h = blockIdx.y;
    int qb = gridDim.x - 1 - blockIdx.x;   // heavy tiles first
    int qbase = qb * 128;
    const int LD = 3 * DIM;

    const __half* Qg = QKV + (size_t)qbase * LD + h * HD;
    const __half* Kg = QKV + DIM + h * HD;
    const __half* Vg = QKV + 2 * DIM + h * HD;

#define ISSUE_KV(i, b)                                                        \
    {                                                                         \
        int kv0_ = (i) * 64;                                                  \
        uint32_t kb_ = sb + 32768 + (b) * 32768;                              \
        _Pragma("unroll") for (int it = 0; it < 4; it++) {                    \
            int id = tid + it * 256;                                          \
            int row = id >> 4, ch = id & 15;                                  \
            uint32_t o_ = (uint32_t)(ch >> 3) * 8192 +                        \
                          sw128_(row * 128 + (ch & 7) * 16);                  \
            const __half* ksrc = Kg + (size_t)(kv0_ + row) * LD + ch * 8;     \
            const __half* vsrc = Vg + (size_t)(kv0_ + row) * LD + ch * 8;     \
            CP16(kb_ + o_, ksrc);                                             \
            CP16(kb_ + 16384 + o_, vsrc);                                     \
        }                                                                     \
    }

#pragma unroll
    for (int it = 0; it < 8; it++) {
        int id = tid + it * 256;
        int row = id >> 4, ch = id & 15;
        uint32_t dst = sb + (uint32_t)(ch >> 3) * 16384 +
                       sw128_(row * 128 + (ch & 7) * 16);
        CP16(dst, Qg + (size_t)row * LD + ch * 8);
    }
    ISSUE_KV(0, 0);
    CP_COMMIT();

    float oacc[16][4];
#pragma unroll
    for (int j = 0; j < 16; j++)
#pragma unroll
        for (int t = 0; t < 4; t++) oacc[j][t] = 0.f;
    float m0 = -1e30f, m1 = -1e30f, l0 = 0.f, l1 = 0.f;
    uint32_t qf[8][4];

    int nkb = qb * 2 + 2;
    int sub = lane >> 3;
    int wrow = qbase + w * 16;

    for (int i = 0; i < nkb; i++) {
        int b = i & 1;
        if (i + 1 < nkb) {
            ISSUE_KV(i + 1, b ^ 1);
            CP_COMMIT();
            CP_WAIT(1);
        } else {
            CP_WAIT(0);
        }
        __syncthreads();
        if (i == 0) {
#pragma unroll
            for (int kt = 0; kt < 8; kt++) {
                int r = w * 16 + (lane & 7) + (sub & 1) * 8;
                uint32_t ch = (uint32_t)((kt & 3) * 2 + (sub >> 1));
                uint32_t addr = sb + (uint32_t)(kt >> 2) * 16384 +
                                sw128_(r * 128 + ch * 16);
                LDSM_X4(qf[kt], addr);
            }
        }
        int kv0 = i * 64;
        if (kv0 <= wrow + 15) {
            float sacc[8][4];
#pragma unroll
            for (int j = 0; j < 8; j++)
#pragma unroll
                for (int t = 0; t < 4; t++) sacc[j][t] = 0.f;
            uint32_t Kb = sb + 32768 + b * 32768;
#pragma unroll
            for (int ng = 0; ng < 4; ng++) {
                int nr = ng * 16 + (sub >> 1) * 8 + (lane & 7);
#pragma unroll
                for (int kt = 0; kt < 8; kt++) {
                    uint32_t bb[4];
                    uint32_t ch = (uint32_t)((kt & 3) * 2 + (sub & 1));
                    uint32_t addr = Kb + (uint32_t)(kt >> 2) * 8192 +
                                    sw128_(nr * 128 + ch * 16);
                    LDSM_X4(bb, addr);
                    MMA_FP16(sacc[ng * 2], qf[kt], bb[0], bb[1]);
                    MMA_FP16(sacc[ng * 2 + 1], qf[kt], bb[2], bb[3]);
                }
            }
            int r0 = wrow + (lane >> 2), r1 = r0 + 8;
            if (kv0 + 63 > r0) {
#pragma unroll
                for (int j = 0; j < 8; j++) {
                    int c = kv0 + j * 8 + 2 * (lane & 3);
                    if (c > r0) sacc[j][0] = -1e30f;
                    if (c + 1 > r0) sacc[j][1] = -1e30f;
                    if (c > r1) sacc[j][2] = -1e30f;
                    if (c + 1 > r1) sacc[j][3] = -1e30f;
                }
            }
            float mx0 = -1e30f, mx1 = -1e30f;
#pragma unroll
            for (int j = 0; j < 8; j++) {
                mx0 = fmaxf(mx0, fmaxf(sacc[j][0], sacc[j][1]));
                mx1 = fmaxf(mx1, fmaxf(sacc[j][2], sacc[j][3]));
            }
            mx0 = fmaxf(mx0, __shfl_xor_sync(~0u, mx0, 1));
            mx0 = fmaxf(mx0, __shfl_xor_sync(~0u, mx0, 2));
            mx1 = fmaxf(mx1, __shfl_xor_sync(~0u, mx1, 1));
            mx1 = fmaxf(mx1, __shfl_xor_sync(~0u, mx1, 2));
            float m0n = fmaxf(m0, mx0), m1n = fmaxf(m1, mx1);
            float c0 = exp2f(m0 - m0n), c1 = exp2f(m1 - m1n);
            float rs0 = 0.f, rs1 = 0.f;
#pragma unroll
            for (int j = 0; j < 8; j++) {
                sacc[j][0] = exp2f(sacc[j][0] - m0n);
                sacc[j][1] = exp2f(sacc[j][1] - m0n);
                sacc[j][2] = exp2f(sacc[j][2] - m1n);
                sacc[j][3] = exp2f(sacc[j][3] - m1n);
                rs0 += sacc[j][0] + sacc[j][1];
                rs1 += sacc[j][2] + sacc[j][3];
            }
            rs0 += __shfl_xor_sync(~0u, rs0, 1);
            rs0 += __shfl_xor_sync(~0u, rs0, 2);
            rs1 += __shfl_xor_sync(~0u, rs1, 1);
            rs1 += __shfl_xor_sync(~0u, rs1, 2);
            l0 = l0 * c0 + rs0;
            l1 = l1 * c1 + rs1;
            m0 = m0n;
            m1 = m1n;
#pragma unroll
            for (int j = 0; j < 16; j++) {
                oacc[j][0] *= c0; oacc[j][1] *= c0;
                oacc[j][2] *= c1; oacc[j][3] *= c1;
            }
            uint32_t Vb = Kb + 16384;
#pragma unroll
            for (int kt = 0; kt < 4; kt++) {
                uint32_t a[4];
                a[0] = cvt2h(sacc[2 * kt][0], sacc[2 * kt][1]);
                a[1] = cvt2h(sacc[2 * kt][2], sacc[2 * kt][3]);
                a[2] = cvt2h(sacc[2 * kt + 1][0], sacc[2 * kt + 1][1]);
                a[3] = cvt2h(sacc[2 * kt + 1][2], sacc[2 * kt + 1][3]);
                int kr = kt * 16 + (lane & 7) + ((lane >> 3) & 1) * 8;
#pragma unroll
                for (int dp = 0; dp < 8; dp++) {
                    int dim = dp * 16 + ((lane >> 4) & 1) * 8;
                    uint32_t addr = Vb + (uint32_t)(dim >> 6) * 8192 +
                                    sw128_(kr * 128 + ((dim & 63) >> 3) * 16);
                    uint32_t vv[4];
                    LDSM_X4_T(vv, addr);
                    MMA_FP16(oacc[dp * 2], a, vv[0], vv[1]);
                    MMA_FP16(oacc[dp * 2 + 1], a, vv[2], vv[3]);
                }
            }
        }
        __syncthreads();
    }

    float i0 = 1.f / l0, i1 = 1.f / l1;
    int r0g = qbase + w * 16 + (lane >> 2);
#pragma unroll
    for (int j = 0; j < 16; j++) {
        int col = h * HD + j * 8 + 2 * (lane & 3);
        *(uint32_t*)(O + (size_t)r0g * DIM + col) =
            cvt2h(oacc[j][0] * i0, oacc[j][1] * i0);
        *(uint32_t*)(O + (size_t)(r0g + 8) * DIM + col) =
            cvt2h(oacc[j][2] * i1, oacc[j][3] * i1);
    }
#undef ISSUE_KV
}

// ---------------- launch ----------------
extern "C" void kernel_launch(void* const* d_in, const int* in_sizes, int n_in,
                              void* d_out, int out_size) {
    const float* x   = (const float*)d_in[0];
    const float* fc  = (const float*)d_in[1];
    const float* fs  = (const float*)d_in[2];
    const float* anw = (const float*)d_in[4];
    const float* wq  = (const float*)d_in[5];
    const float* wk  = (const float*)d_in[6];
    const float* wv  = (const float*)d_in[7];
    const float* wo  = (const float*)d_in[8];
    const float* fnw = (const float*)d_in[9];
    const float* w1  = (const float*)d_in[10];
    const float* w2  = (const float*)d_in[11];
    const float* w3  = (const float*)d_in[12];
    float* out = (float*)d_out;

    float* h;
    __half *xnh, *qkvh, *ath, *gh;
    __half *wqkvh, *woh, *w13h, *w2h;
    cudaGetSymbolAddress((void**)&h,     g_h);
    cudaGetSymbolAddress((void**)&xnh,   g_xnh);
    cudaGetSymbolAddress((void**)&qkvh,  g_qkvh);
    cudaGetSymbolAddress((void**)&ath,   g_ath);
    cudaGetSymbolAddress((void**)&gh,    g_gh);
    cudaGetSymbolAddress((void**)&wqkvh, g_wqkvh);
    cudaGetSymbolAddress((void**)&woh,   g_woh);
    cudaGetSymbolAddress((void**)&w13h,  g_w13h);
    cudaGetSymbolAddress((void**)&w2h,   g_w2h);

    cudaFuncSetAttribute(gemm_p<0>, cudaFuncAttributeMaxDynamicSharedMemorySize, GEMM_SMEM);
    cudaFuncSetAttribute(gemm_p<2>, cudaFuncAttributeMaxDynamicSharedMemorySize, GEMM_SMEM);
    cudaFuncSetAttribute(gemm_p<3>, cudaFuncAttributeMaxDynamicSharedMemorySize, GEMM_SMEM);
    cudaFuncSetAttribute(flash_attn, cudaFuncAttributeMaxDynamicSharedMemorySize, FA_SMEM);

    const int ndd4 = DIM * DIM / 4;
    const int nhd4 = HID * DIM / 4;
    convert_kernel<<<(ndd4 + 255) / 256, 256>>>(wq, wqkvh, ndd4);
    convert_kernel<<<(ndd4 + 255) / 256, 256>>>(wk, wqkvh + (size_t)DIM * DIM, ndd4);
    convert_kernel<<<(ndd4 + 255) / 256, 256>>>(wv, wqkvh + (size_t)2 * DIM * DIM, ndd4);
    convert_kernel<<<(ndd4 + 255) / 256, 256>>>(wo, woh, ndd4);
    convert_w13<<<(nhd4 + 255) / 256, 256>>>(w1, w3, w13h, nhd4);
    convert_kernel<<<(nhd4 + 255) / 256, 256>>>(w2, w2h, nhd4);

    // 1. xn = rmsnorm(x)
    rmsnorm_h<<<SEQ, 256>>>(x, anw, xnh);
    // 2+3. qkv = xn @ [wq;wk;wv]^T with fused RoPE (fp16 out)
    gemm_p<3><<<GEMM_GRID, 256, GEMM_SMEM>>>(xnh, wqkvh, nullptr, fc, fs,
                                             qkvh, SEQ, 3 * DIM, DIM);
    // 4. flash attention
    flash_attn<<<dim3(SEQ / 128, NH), 256, FA_SMEM>>>(qkvh, ath);
    // 5. h = x + attn @ wo^T
    gemm_p<0><<<GEMM_GRID, 256, GEMM_SMEM>>>(ath, woh, x, nullptr, nullptr,
                                             h, SEQ, DIM, DIM);
    // 6. hn = rmsnorm(h)
    rmsnorm_h<<<SEQ, 256>>>(h, fnw, xnh);
    // 7+8. g = silu(hn@w1^T) * (hn@w3^T)   (fused swiglu epilogue)
    gemm_p<2><<<GEMM_GRID, 256, GEMM_SMEM>>>(xnh, w13h, nullptr, nullptr, nullptr,
                                             gh, SEQ, 2 * HID, DIM);
    // 9. out = h + g @ w2^T
    gemm_p<0><<<GEMM_GRID, 256, GEMM_SMEM>>>(gh, w2h, h, nullptr, nullptr,
                                             out, SEQ, DIM, HID);
}